// round 11
// baseline (speedup 1.0000x reference)
#include <cuda_runtime.h>
#include <cfloat>

#define Bn 16
#define Cn 64
#define Nn 2048
#define On 64
#define Kn 20
#define CNT_TOT (16*2048*20)

// ---------------- scratch (static device globals; no runtime allocation) ----------------
__device__ float  g_D[(size_t)Bn*Nn*Nn];     // 256 MB neg_dist scratch
__device__ float  g_xx[Bn*Nn];               // squared norms
__device__ int    g_idx[Bn*Nn*Kn];           // top-K index sets (order arbitrary)
__device__ float  g_U[(size_t)Bn*Nn*On];     // U[b][m][o] = Wd . x  (o contiguous)
__device__ float  g_Bse[(size_t)Bn*Nn*On];   // (V-U)[b][n][o]
__device__ double g_sum[On], g_sumsq[On];
__device__ float  g_scale[On], g_shift[On];

// ---------------- kernel 0: zero the stats accumulators (graph replays!) ----------------
__global__ void k_zero() {
    int o = threadIdx.x;
    g_sum[o] = 0.0; g_sumsq[o] = 0.0;
}

// ---------------- kernel 1: xx[b,n] = sum_c x^2 ----------------
__global__ void k_xx(const float* __restrict__ x) {
    int id = blockIdx.x * blockDim.x + threadIdx.x;   // 0 .. B*N-1
    if (id >= Bn * Nn) return;
    int b = id / Nn, n = id % Nn;
    const float* xp = x + (size_t)b * Cn * Nn + n;
    float s = 0.f;
#pragma unroll
    for (int c = 0; c < Cn; c++) {
        float v = xp[(size_t)c * Nn];
        s = fmaf(v, v, s);
    }
    g_xx[id] = s;
}

// ---------------- kernel 2: neg_dist 128x128 tiles, 8x8 per thread ----------------
// Triangular grid (tm >= tn); mirror written via smem transpose.
__global__ void __launch_bounds__(256) k_gram(const float* __restrict__ x) {
    __shared__ __align__(16) float sh[64 * 132];   // As|Bs during compute, Ts after

    int t = blockIdx.x, b = blockIdx.y;
    int tm = (int)((sqrtf(8.f * t + 1.f) - 1.f) * 0.5f);
    while ((tm + 1) * (tm + 2) / 2 <= t) tm++;
    while (tm * (tm + 1) / 2 > t) tm--;
    int tn = t - tm * (tm + 1) / 2;

    int n0 = tn * 128, m0 = tm * 128;
    const float* xb = x + (size_t)b * Cn * Nn;
    int tid = threadIdx.x, tx = tid & 15, ty = tid >> 4;

    float* As = sh;            // [32][128]
    float* Bs = sh + 32 * 128; // [32][128]

    float acc[8][8] = {};

    for (int kc = 0; kc < 64; kc += 32) {
        __syncthreads();
#pragma unroll
        for (int i = 0; i < 4; i++) {
            int f = tid + 256 * i;          // float4 index over 1024
            int c = f >> 5, c4 = (f & 31) * 4;
            *(float4*)&As[c * 128 + c4] = *(const float4*)&xb[(size_t)(kc + c) * Nn + n0 + c4];
            *(float4*)&Bs[c * 128 + c4] = *(const float4*)&xb[(size_t)(kc + c) * Nn + m0 + c4];
        }
        __syncthreads();
#pragma unroll 4
        for (int c = 0; c < 32; c++) {
            float4 a0 = *(float4*)&As[c * 128 + ty * 4];
            float4 a1 = *(float4*)&As[c * 128 + 64 + ty * 4];
            float4 b0 = *(float4*)&Bs[c * 128 + tx * 4];
            float4 b1 = *(float4*)&Bs[c * 128 + 64 + tx * 4];
            float av[8] = {a0.x, a0.y, a0.z, a0.w, a1.x, a1.y, a1.z, a1.w};
            float bv[8] = {b0.x, b0.y, b0.z, b0.w, b1.x, b1.y, b1.z, b1.w};
#pragma unroll
            for (int i = 0; i < 8; i++)
#pragma unroll
                for (int j = 0; j < 8; j++)
                    acc[i][j] = fmaf(av[i], bv[j], acc[i][j]);
        }
    }

    float xn[8], xm[8];
#pragma unroll
    for (int i = 0; i < 4; i++) {
        xn[i]     = g_xx[b * Nn + n0 + ty * 4 + i];
        xn[4 + i] = g_xx[b * Nn + n0 + 64 + ty * 4 + i];
        xm[i]     = g_xx[b * Nn + m0 + tx * 4 + i];
        xm[4 + i] = g_xx[b * Nn + m0 + 64 + tx * 4 + i];
    }

    float vv[8][8];
#pragma unroll
    for (int i = 0; i < 8; i++)
#pragma unroll
        for (int j = 0; j < 8; j++)
            vv[i][j] = 2.f * acc[i][j] - xn[i] - xm[j];

    float* Db = g_D + (size_t)b * Nn * Nn;

    // direct store: D[n][m]
#pragma unroll
    for (int i = 0; i < 8; i++) {
        int nl = (i < 4) ? (ty * 4 + i) : (64 + ty * 4 + i - 4);
        *(float4*)&Db[(size_t)(n0 + nl) * Nn + m0 + tx * 4] =
            make_float4(vv[i][0], vv[i][1], vv[i][2], vv[i][3]);
        *(float4*)&Db[(size_t)(n0 + nl) * Nn + m0 + 64 + tx * 4] =
            make_float4(vv[i][4], vv[i][5], vv[i][6], vv[i][7]);
    }

    // mirror store: D[m][n] via smem transpose (two 64-col halves)
    if (tm != tn) {
        float* Ts = sh;                       // [64][132]
#pragma unroll
        for (int h = 0; h < 2; h++) {
            __syncthreads();
#pragma unroll
            for (int i = 0; i < 8; i++) {
                int nl = (i < 4) ? (ty * 4 + i) : (64 + ty * 4 + i - 4);
#pragma unroll
                for (int j = 0; j < 4; j++)
                    Ts[(tx * 4 + j) * 132 + nl] = vv[i][h * 4 + j];
            }
            __syncthreads();
#pragma unroll
            for (int q = 0; q < 8; q++) {
                int f = tid + 256 * q;        // over 64*32 float4
                int mc = f >> 5, n4 = (f & 31) * 4;
                float4 w = *(float4*)&Ts[mc * 132 + n4];
                *(float4*)&Db[(size_t)(m0 + h * 64 + mc) * Nn + n0 + n4] = w;
            }
        }
    }
}

// ---------------- kernel 3: top-K=20 per row via sampled threshold + 1 count pass ------
// thr = min over warps of (warp max of one sample/thread): order statistics put
// count(>= thr) at ~136 (P>512 ~ 8e-4, P<20 ~ 3e-5). One count pass verifies;
// candidates are collected and ranked exactly by (value desc, idx asc) ->
// identical set to stable top_k (only the SET matters downstream). Rare rows
// expand/narrow; mass-tie pathology falls back to exact iterative argmax.
#define TOPK_COUNT(T, OUT) do {                                     \
    int c_ = 0;                                                     \
    _Pragma("unroll")                                               \
    for (int i_ = 0; i_ < 8; i_++) c_ += (f[i_] >= (T));            \
    c_ = __reduce_add_sync(0xffffffffu, c_);                        \
    if (lane == 0 && c_) atomicAdd(&s_c[p], c_);                    \
    if (tid == 0) s_c[p ^ 1] = 0;                                   \
    __syncthreads();                                                \
    (OUT) = s_c[p];                                                 \
    p ^= 1;                                                         \
} while (0)

__global__ void __launch_bounds__(256) k_topk() {
    int row = blockIdx.x;                       // b*N + n
    const float4* d4 = (const float4*)(g_D + (size_t)row * Nn);
    int tid = threadIdx.x;                      // 256 threads, 8 elems each
    int lane = tid & 31, warp = tid >> 5;

    __shared__ float s_wmax[8];
    __shared__ int   s_c[2];
    __shared__ int   s_cc;
    __shared__ float          cv[512];
    __shared__ unsigned short cix[512];
    __shared__ float sv[8];
    __shared__ int   si[8];
    __shared__ int   swin;

    float4 a = d4[tid * 2], b4 = d4[tid * 2 + 1];
    float f[8] = {a.x, a.y, a.z, a.w, b4.x, b4.y, b4.z, b4.w};

    // sampled threshold: min over warps of warp-max of f[0]
    float s = f[0];
#pragma unroll
    for (int off = 16; off; off >>= 1) s = fmaxf(s, __shfl_xor_sync(0xffffffffu, s, off));
    if (lane == 0) s_wmax[warp] = s;
    if (tid < 2) s_c[tid] = 0;
    if (tid == 0) s_cc = 0;
    __syncthreads();

    float thr = s_wmax[0];
#pragma unroll
    for (int w = 1; w < 8; w++) thr = fminf(thr, s_wmax[w]);

    int p = 0;
    int cnt;
    TOPK_COUNT(thr, cnt);

    float lo = thr, hi = 0.f;
    int cnt_lo = cnt;

    // rare: too few -> expand downward (thr' = 2*thr - 10 moves fast from any scale)
    for (int it = 0; it < 60 && cnt_lo < Kn; it++) {
        hi = lo;
        lo = 2.f * lo - 10.f;
        TOPK_COUNT(lo, cnt_lo);
    }
    // rare: too many -> binary narrow (invariant: count(>= lo) >= K)
    for (int it = 0; it < 30 && cnt_lo > 512; it++) {
        float mid = 0.5f * (lo + hi);
        if (!(mid > lo && mid < hi)) break;     // interval collapsed (mass ties)
        int cm;
        TOPK_COUNT(mid, cm);
        if (cm >= Kn) { lo = mid; cnt_lo = cm; } else hi = mid;
    }

    int* op = g_idx + row * Kn;

    if (cnt_lo >= Kn && cnt_lo <= 512) {
        // collect candidates and rank exactly by (value desc, idx asc)
#pragma unroll
        for (int i = 0; i < 8; i++) {
            if (f[i] >= lo) {
                int q = atomicAdd(&s_cc, 1);
                cv[q] = f[i]; cix[q] = (unsigned short)(tid * 8 + i);
            }
        }
        __syncthreads();
        int cc = s_cc;                           // == cnt_lo
        for (int i = tid; i < cc; i += 256) {
            float vi = cv[i]; int xi = cix[i];
            int r = 0;
            for (int j = 0; j < cc; j++) {
                float vj = cv[j];
                r += (vj > vi) || (vj == vi && cix[j] < xi);
            }
            if (r < Kn) op[r] = xi;
        }
        return;                                  // uniform: cnt_lo is block-uniform
    }

    // pathological fallback: exact iterative argmax
    for (int k = 0; k < Kn; k++) {
        float bv = -FLT_MAX;
        int   bi = 0x7fffffff;
#pragma unroll
        for (int i = 0; i < 8; i++) {
            int e = tid + (i << 8);
            if (f[i] > bv) { bv = f[i]; bi = e; }
        }
#pragma unroll
        for (int off = 16; off; off >>= 1) {
            float ov = __shfl_down_sync(0xffffffffu, bv, off);
            int   oi = __shfl_down_sync(0xffffffffu, bi, off);
            if (ov > bv || (ov == bv && oi < bi)) { bv = ov; bi = oi; }
        }
        if ((tid & 31) == 0) { sv[tid >> 5] = bv; si[tid >> 5] = bi; }
        __syncthreads();
        if (tid == 0) {
            float fv = sv[0]; int fi = si[0];
#pragma unroll
            for (int w = 1; w < 8; w++)
                if (sv[w] > fv || (sv[w] == fv && si[w] < fi)) { fv = sv[w]; fi = si[w]; }
            swin = fi;
            op[k] = fi;
        }
        __syncthreads();
        int w = swin;
        if ((w & 255) == tid) f[w >> 8] = -FLT_MAX;
    }
}

// ---------------- kernel 4: U = Wd.x , Bse = (Wc-Wd).x  (o-contiguous layout) -----------
__global__ void k_uv(const float* __restrict__ x, const float* __restrict__ W) {
    int b = blockIdx.y;
    int m0 = blockIdx.x * 64;
    __shared__ float Wd[64 * 64];   // [c][o]
    __shared__ float Wf[64 * 64];   // [c][o]  (Wc - Wd)
    __shared__ float xs[64 * 64];   // [c][m]
    int tid = threadIdx.x;
#pragma unroll
    for (int i = 0; i < 16; i++) {
        int id = tid + 256 * i;
        int o = id >> 6, c = id & 63;
        float wd = W[o * 128 + c];
        float wc = W[o * 128 + 64 + c];
        Wd[c * 64 + o] = wd;
        Wf[c * 64 + o] = wc - wd;
        xs[id] = x[(size_t)b * Cn * Nn + (size_t)(id >> 6) * Nn + m0 + (id & 63)];
    }
    __syncthreads();

    int o = tid & 63, mq = tid >> 6;
    float aU[16], aD[16];
#pragma unroll
    for (int t = 0; t < 16; t++) { aU[t] = 0.f; aD[t] = 0.f; }

    for (int c = 0; c < 64; c++) {
        float wu = Wd[c * 64 + o];
        float wf = Wf[c * 64 + o];
#pragma unroll
        for (int t = 0; t < 16; t++) {
            float xv = xs[c * 64 + mq + t * 4];   // broadcast within warp
            aU[t] = fmaf(wu, xv, aU[t]);
            aD[t] = fmaf(wf, xv, aD[t]);
        }
    }
#pragma unroll
    for (int t = 0; t < 16; t++) {
        int m = m0 + mq + t * 4;
        g_U  [((size_t)b * Nn + m) * On + o] = aU[t];
        g_Bse[((size_t)b * Nn + m) * On + o] = aD[t];
    }
}

// ---------------- kernel 5: per-channel sum / sumsq of y over (b,n,k) ----------------
__global__ void k_stats() {
    int b = blockIdx.y;
    int n0 = blockIdx.x * 128;
    int tid = threadIdx.x;
    int o = tid & 63, g = tid >> 6;
    float s = 0.f, s2 = 0.f;
    for (int j = 0; j < 32; j++) {
        int n = n0 + g * 32 + j;
        float bse = g_Bse[((size_t)b * Nn + n) * On + o];
        const int* ip = g_idx + (b * Nn + n) * Kn;
#pragma unroll
        for (int k = 0; k < Kn; k++) {
            int m = ip[k];
            float y = g_U[((size_t)b * Nn + m) * On + o] + bse;
            s += y;
            s2 = fmaf(y, y, s2);
        }
    }
    __shared__ float ss[4][64], ss2[4][64];
    ss[g][o] = s; ss2[g][o] = s2;
    __syncthreads();
    if (g == 0) {
        double ts = (double)ss[0][o] + (double)ss[1][o] + (double)ss[2][o] + (double)ss[3][o];
        double t2 = (double)ss2[0][o] + (double)ss2[1][o] + (double)ss2[2][o] + (double)ss2[3][o];
        atomicAdd(&g_sum[o], ts);
        atomicAdd(&g_sumsq[o], t2);
    }
}

// ---------------- kernel 6: finalize BN affine ----------------
__global__ void k_fin(const float* __restrict__ gamma, const float* __restrict__ beta) {
    int o = threadIdx.x;
    double mean = g_sum[o] / (double)CNT_TOT;
    double var  = g_sumsq[o] / (double)CNT_TOT - mean * mean;
    float sc = gamma[o] * rsqrtf((float)var + 1e-5f);
    g_scale[o] = sc;
    g_shift[o] = beta[o] - (float)mean * sc;
}

// ---------------- kernel 7: normalize + leaky relu + max over k -> out[b][o][n] --------
__global__ void k_out(float* __restrict__ out) {
    int b = blockIdx.y;
    int n0 = blockIdx.x * 32;
    int tid = threadIdx.x;
    int o = tid & 63, nq = tid >> 6;
    __shared__ float sm[64 * 33];
    float sc = g_scale[o], sh = g_shift[o];
    for (int j = 0; j < 8; j++) {
        int nl = nq * 8 + j;
        int n = n0 + nl;
        float bse = g_Bse[((size_t)b * Nn + n) * On + o];
        const int* ip = g_idx + (b * Nn + n) * Kn;
        float mx = -FLT_MAX;
#pragma unroll
        for (int k = 0; k < Kn; k++) {
            int m = ip[k];
            float y  = g_U[((size_t)b * Nn + m) * On + o] + bse;
            float yn = fmaf(y, sc, sh);
            float a  = (yn >= 0.f) ? yn : 0.2f * yn;
            mx = fmaxf(mx, a);
        }
        sm[o * 33 + nl] = mx;
    }
    __syncthreads();
    int nl2 = tid & 31, og = tid >> 5;
#pragma unroll
    for (int j = 0; j < 8; j++) {
        int o2 = og * 8 + j;
        out[((size_t)b * On + o2) * Nn + n0 + nl2] = sm[o2 * 33 + nl2];
    }
}

// ---------------- launch ----------------
extern "C" void kernel_launch(void* const* d_in, const int* in_sizes, int n_in,
                              void* d_out, int out_size) {
    const float* x     = (const float*)d_in[0];
    const float* W     = (const float*)d_in[1];
    const float* gamma = (const float*)d_in[2];
    const float* beta  = (const float*)d_in[3];
    float* out = (float*)d_out;

    k_zero<<<1, 64>>>();
    k_xx<<<(Bn * Nn) / 256, 256>>>(x);

    dim3 gg(136, 16);                 // triangular tile set, 128x128 tiles
    k_gram<<<gg, 256>>>(x);

    k_topk<<<Bn * Nn, 256>>>();

    dim3 guv(Nn / 64, Bn);
    k_uv<<<guv, 256>>>(x, W);

    dim3 gst(16, Bn);
    k_stats<<<gst, 256>>>();

    k_fin<<<1, 64>>>(gamma, beta);

    dim3 go(Nn / 32, Bn);
    k_out<<<go, 256>>>(out);
}

// round 13
// speedup vs baseline: 2.1901x; 2.1901x over previous
#include <cuda_runtime.h>
#include <cfloat>

#define Bn 16
#define Cn 64
#define Nn 2048
#define On 64
#define Kn 20
#define CNT_TOT (16*2048*20)

// ---------------- scratch (static device globals; no runtime allocation) ----------------
__device__ float  g_D[(size_t)Bn*Nn*Nn];     // 256 MB neg_dist scratch
__device__ float  g_xx[Bn*Nn];               // squared norms
__device__ int    g_idx[Bn*Nn*Kn];           // top-K index sets (order arbitrary)
__device__ float  g_U[(size_t)Bn*Nn*On];     // U[b][m][o] = Wd . x  (o contiguous)
__device__ float  g_Bse[(size_t)Bn*Nn*On];   // (V-U)[b][n][o]
__device__ double g_sum[On], g_sumsq[On];
__device__ float  g_scale[On], g_shift[On];

// ---------------- kernel 0: zero the stats accumulators (graph replays!) ----------------
__global__ void k_zero() {
    int o = threadIdx.x;
    g_sum[o] = 0.0; g_sumsq[o] = 0.0;
}

// ---------------- kernel 1: xx[b,n] = sum_c x^2 ----------------
__global__ void k_xx(const float* __restrict__ x) {
    int id = blockIdx.x * blockDim.x + threadIdx.x;   // 0 .. B*N-1
    if (id >= Bn * Nn) return;
    int b = id / Nn, n = id % Nn;
    const float* xp = x + (size_t)b * Cn * Nn + n;
    float s = 0.f;
#pragma unroll
    for (int c = 0; c < Cn; c++) {
        float v = xp[(size_t)c * Nn];
        s = fmaf(v, v, s);
    }
    g_xx[id] = s;
}

// ---------------- kernel 2: neg_dist 128x128 tiles, 8x8 per thread ----------------
// Triangular grid (tm >= tn); mirror written via smem transpose.
__global__ void __launch_bounds__(256) k_gram(const float* __restrict__ x) {
    __shared__ __align__(16) float sh[64 * 132];   // As|Bs during compute, Ts after

    int t = blockIdx.x, b = blockIdx.y;
    int tm = (int)((sqrtf(8.f * t + 1.f) - 1.f) * 0.5f);
    while ((tm + 1) * (tm + 2) / 2 <= t) tm++;
    while (tm * (tm + 1) / 2 > t) tm--;
    int tn = t - tm * (tm + 1) / 2;

    int n0 = tn * 128, m0 = tm * 128;
    const float* xb = x + (size_t)b * Cn * Nn;
    int tid = threadIdx.x, tx = tid & 15, ty = tid >> 4;

    float* As = sh;            // [32][128]
    float* Bs = sh + 32 * 128; // [32][128]

    float acc[8][8] = {};

    for (int kc = 0; kc < 64; kc += 32) {
        __syncthreads();
#pragma unroll
        for (int i = 0; i < 4; i++) {
            int f = tid + 256 * i;          // float4 index over 1024
            int c = f >> 5, c4 = (f & 31) * 4;
            *(float4*)&As[c * 128 + c4] = *(const float4*)&xb[(size_t)(kc + c) * Nn + n0 + c4];
            *(float4*)&Bs[c * 128 + c4] = *(const float4*)&xb[(size_t)(kc + c) * Nn + m0 + c4];
        }
        __syncthreads();
#pragma unroll 4
        for (int c = 0; c < 32; c++) {
            float4 a0 = *(float4*)&As[c * 128 + ty * 4];
            float4 a1 = *(float4*)&As[c * 128 + 64 + ty * 4];
            float4 b0 = *(float4*)&Bs[c * 128 + tx * 4];
            float4 b1 = *(float4*)&Bs[c * 128 + 64 + tx * 4];
            float av[8] = {a0.x, a0.y, a0.z, a0.w, a1.x, a1.y, a1.z, a1.w};
            float bv[8] = {b0.x, b0.y, b0.z, b0.w, b1.x, b1.y, b1.z, b1.w};
#pragma unroll
            for (int i = 0; i < 8; i++)
#pragma unroll
                for (int j = 0; j < 8; j++)
                    acc[i][j] = fmaf(av[i], bv[j], acc[i][j]);
        }
    }

    float xn[8], xm[8];
#pragma unroll
    for (int i = 0; i < 4; i++) {
        xn[i]     = g_xx[b * Nn + n0 + ty * 4 + i];
        xn[4 + i] = g_xx[b * Nn + n0 + 64 + ty * 4 + i];
        xm[i]     = g_xx[b * Nn + m0 + tx * 4 + i];
        xm[4 + i] = g_xx[b * Nn + m0 + 64 + tx * 4 + i];
    }

    float vv[8][8];
#pragma unroll
    for (int i = 0; i < 8; i++)
#pragma unroll
        for (int j = 0; j < 8; j++)
            vv[i][j] = 2.f * acc[i][j] - xn[i] - xm[j];

    float* Db = g_D + (size_t)b * Nn * Nn;

    // direct store: D[n][m]
#pragma unroll
    for (int i = 0; i < 8; i++) {
        int nl = (i < 4) ? (ty * 4 + i) : (64 + ty * 4 + i - 4);
        *(float4*)&Db[(size_t)(n0 + nl) * Nn + m0 + tx * 4] =
            make_float4(vv[i][0], vv[i][1], vv[i][2], vv[i][3]);
        *(float4*)&Db[(size_t)(n0 + nl) * Nn + m0 + 64 + tx * 4] =
            make_float4(vv[i][4], vv[i][5], vv[i][6], vv[i][7]);
    }

    // mirror store: D[m][n] via smem transpose (two 64-col halves)
    if (tm != tn) {
        float* Ts = sh;                       // [64][132]
#pragma unroll
        for (int h = 0; h < 2; h++) {
            __syncthreads();
#pragma unroll
            for (int i = 0; i < 8; i++) {
                int nl = (i < 4) ? (ty * 4 + i) : (64 + ty * 4 + i - 4);
#pragma unroll
                for (int j = 0; j < 4; j++)
                    Ts[(tx * 4 + j) * 132 + nl] = vv[i][h * 4 + j];
            }
            __syncthreads();
#pragma unroll
            for (int q = 0; q < 8; q++) {
                int f = tid + 256 * q;        // over 64*32 float4
                int mc = f >> 5, n4 = (f & 31) * 4;
                float4 w = *(float4*)&Ts[mc * 132 + n4];
                *(float4*)&Db[(size_t)(m0 + h * 64 + mc) * Nn + n0 + n4] = w;
            }
        }
    }
}

// ---------------- kernel 3: top-K=20: sampled threshold + sparse histogram select ------
// thr = min over warps of (warp max of one sample/thread) -> count(>= thr) ~ 170.
// Only elements >= thr enter a 256-bin histogram over [thr, 0] (monotone map);
// suffix scan finds the bin containing the 20th largest; bins above it are
// emitted directly (only the SET matters downstream); the threshold bin (~1-3
// elems) gets exact (value desc, idx asc) rank -> identical set to stable
// top_k. Degenerate cases (count<K, thr~0, fat threshold bin) fall back to
// exact iterative argmax. NOTE: f[i] holds element tid*8 + i (contiguous
// float4 loads) -- fallback indexing must match.
__global__ void __launch_bounds__(256) k_topk() {
    int row = blockIdx.x;                       // b*N + n
    const float4* d4 = (const float4*)(g_D + (size_t)row * Nn);
    int tid = threadIdx.x;                      // 256 threads, 8 elems each
    int lane = tid & 31, warp = tid >> 5;

    __shared__ float s_wmax[8];
    __shared__ int   hist[257];                 // suffix-scanned in place
    __shared__ int   s_c, s_win, s_kp, s_cnt, s_tb;
    __shared__ float          cv[64];
    __shared__ unsigned short cix[64];
    __shared__ float sv[8];
    __shared__ int   si[8];
    __shared__ int   swin;

    float4 a = d4[tid * 2], b4 = d4[tid * 2 + 1];
    float f[8] = {a.x, a.y, a.z, a.w, b4.x, b4.y, b4.z, b4.w};

    // sampled threshold: min over warps of warp-max of f[0]
    float s = f[0];
#pragma unroll
    for (int off = 16; off; off >>= 1) s = fmaxf(s, __shfl_xor_sync(0xffffffffu, s, off));
    if (lane == 0) s_wmax[warp] = s;
    hist[tid] = 0;
    if (tid == 0) { hist[256] = 0; s_c = 0; s_cnt = 0; s_tb = 0; }
    __syncthreads();

    float thr = s_wmax[0];
#pragma unroll
    for (int w = 1; w < 8; w++) thr = fminf(thr, s_wmax[w]);

    bool fb = (thr > -1e-20f);                  // degenerate: many ~zero dists

    int bin[8];
    if (!fb) {
        float scale = 255.f / (-thr);
        int c = 0;
#pragma unroll
        for (int i = 0; i < 8; i++) {
            if (f[i] >= thr) {
                c++;
                int bb = (int)((f[i] - thr) * scale);
                bb = bb > 255 ? 255 : bb;
                bin[i] = bb;
                atomicAdd(&hist[bb], 1);
            } else bin[i] = -1;
        }
        c = __reduce_add_sync(0xffffffffu, c);
        if (lane == 0 && c) atomicAdd(&s_c, c);
    }
    __syncthreads();

    if (!fb && s_c >= Kn) {
        // suffix counts in place: hist[b] = #elems(>=thr) with bin >= b (warp 0)
        if (tid < 32) {
            int base = tid * 8, l[8], run = 0;
#pragma unroll
            for (int j = 7; j >= 0; j--) { run += hist[base + j]; l[j] = run; }
            int tot = run, inc = tot;
#pragma unroll
            for (int off = 1; off < 32; off <<= 1) {
                int v = __shfl_down_sync(0xffffffffu, inc, off);
                if (tid + off < 32) inc += v;
            }
            int above = inc - tot;
#pragma unroll
            for (int j = 0; j < 8; j++) hist[base + j] = l[j] + above;
        }
        __syncthreads();
        {
            int cg = hist[tid], cgn = hist[tid + 1];
            if (cg >= Kn && cgn < Kn) { s_win = tid; s_kp = Kn - cgn; }
        }
        __syncthreads();

        int win = s_win, kp = s_kp;
        int tb = hist[win] - hist[win + 1];     // threshold-bin population (uniform)

        if (tb <= 64) {
            int* op = g_idx + row * Kn;
            // direct emit (bins > win, order arbitrary) + collect threshold bin
#pragma unroll
            for (int i = 0; i < 8; i++) {
                if (bin[i] > win) {
                    op[atomicAdd(&s_cnt, 1)] = tid * 8 + i;
                } else if (bin[i] == win) {
                    int q = atomicAdd(&s_tb, 1);
                    cv[q] = f[i]; cix[q] = (unsigned short)(tid * 8 + i);
                }
            }
            __syncthreads();
            int cc = s_tb, base = s_cnt;        // base == Kn - kp
            // exact rank in threshold bin by (value desc, idx asc); cc ~ 1-3
            for (int i = tid; i < cc; i += 256) {
                float vi = cv[i]; int xi = cix[i];
                int r = 0;
                for (int j = 0; j < cc; j++) {
                    float vj = cv[j];
                    r += (vj > vi) || (vj == vi && cix[j] < xi);
                }
                if (r < kp) op[base + r] = xi;
            }
            return;                             // uniform: win/tb block-uniform
        }
        // fat threshold bin: fall through to exact fallback
    }

    // exact fallback: iterative argmax (rare). f[i] = element tid*8 + i.
    int* op = g_idx + row * Kn;
    for (int k = 0; k < Kn; k++) {
        float bv = -FLT_MAX;
        int   bi = 0x7fffffff;
#pragma unroll
        for (int i = 0; i < 8; i++) {
            int e = tid * 8 + i;
            if (f[i] > bv) { bv = f[i]; bi = e; }   // i asc -> smallest e on tie
        }
#pragma unroll
        for (int off = 16; off; off >>= 1) {
            float ov = __shfl_down_sync(0xffffffffu, bv, off);
            int   oi = __shfl_down_sync(0xffffffffu, bi, off);
            if (ov > bv || (ov == bv && oi < bi)) { bv = ov; bi = oi; }
        }
        if ((tid & 31) == 0) { sv[tid >> 5] = bv; si[tid >> 5] = bi; }
        __syncthreads();
        if (tid == 0) {
            float fv = sv[0]; int fi = si[0];
#pragma unroll
            for (int w = 1; w < 8; w++)
                if (sv[w] > fv || (sv[w] == fv && si[w] < fi)) { fv = sv[w]; fi = si[w]; }
            swin = fi;
            op[k] = fi;
        }
        __syncthreads();
        int w = swin;
        if ((w >> 3) == tid) f[w & 7] = -FLT_MAX;   // element w lives in thread w/8 slot w%8
    }
}

// ---------------- kernel 4: U = Wd.x , Bse = (Wc-Wd).x  (o-contiguous layout) -----------
__global__ void k_uv(const float* __restrict__ x, const float* __restrict__ W) {
    int b = blockIdx.y;
    int m0 = blockIdx.x * 64;
    __shared__ float Wd[64 * 64];   // [c][o]
    __shared__ float Wf[64 * 64];   // [c][o]  (Wc - Wd)
    __shared__ float xs[64 * 64];   // [c][m]
    int tid = threadIdx.x;
#pragma unroll
    for (int i = 0; i < 16; i++) {
        int id = tid + 256 * i;
        int o = id >> 6, c = id & 63;
        float wd = W[o * 128 + c];
        float wc = W[o * 128 + 64 + c];
        Wd[c * 64 + o] = wd;
        Wf[c * 64 + o] = wc - wd;
        xs[id] = x[(size_t)b * Cn * Nn + (size_t)(id >> 6) * Nn + m0 + (id & 63)];
    }
    __syncthreads();

    int o = tid & 63, mq = tid >> 6;
    float aU[16], aD[16];
#pragma unroll
    for (int t = 0; t < 16; t++) { aU[t] = 0.f; aD[t] = 0.f; }

    for (int c = 0; c < 64; c++) {
        float wu = Wd[c * 64 + o];
        float wf = Wf[c * 64 + o];
#pragma unroll
        for (int t = 0; t < 16; t++) {
            float xv = xs[c * 64 + mq + t * 4];   // broadcast within warp
            aU[t] = fmaf(wu, xv, aU[t]);
            aD[t] = fmaf(wf, xv, aD[t]);
        }
    }
#pragma unroll
    for (int t = 0; t < 16; t++) {
        int m = m0 + mq + t * 4;
        g_U  [((size_t)b * Nn + m) * On + o] = aU[t];
        g_Bse[((size_t)b * Nn + m) * On + o] = aD[t];
    }
}

// ---------------- kernel 5: per-channel sum / sumsq of y over (b,n,k) ----------------
__global__ void k_stats() {
    int b = blockIdx.y;
    int n0 = blockIdx.x * 128;
    int tid = threadIdx.x;
    int o = tid & 63, g = tid >> 6;
    float s = 0.f, s2 = 0.f;
    for (int j = 0; j < 32; j++) {
        int n = n0 + g * 32 + j;
        float bse = g_Bse[((size_t)b * Nn + n) * On + o];
        const int* ip = g_idx + (b * Nn + n) * Kn;
#pragma unroll
        for (int k = 0; k < Kn; k++) {
            int m = ip[k];
            float y = g_U[((size_t)b * Nn + m) * On + o] + bse;
            s += y;
            s2 = fmaf(y, y, s2);
        }
    }
    __shared__ float ss[4][64], ss2[4][64];
    ss[g][o] = s; ss2[g][o] = s2;
    __syncthreads();
    if (g == 0) {
        double ts = (double)ss[0][o] + (double)ss[1][o] + (double)ss[2][o] + (double)ss[3][o];
        double t2 = (double)ss2[0][o] + (double)ss2[1][o] + (double)ss2[2][o] + (double)ss2[3][o];
        atomicAdd(&g_sum[o], ts);
        atomicAdd(&g_sumsq[o], t2);
    }
}

// ---------------- kernel 6: finalize BN affine ----------------
__global__ void k_fin(const float* __restrict__ gamma, const float* __restrict__ beta) {
    int o = threadIdx.x;
    double mean = g_sum[o] / (double)CNT_TOT;
    double var  = g_sumsq[o] / (double)CNT_TOT - mean * mean;
    float sc = gamma[o] * rsqrtf((float)var + 1e-5f);
    g_scale[o] = sc;
    g_shift[o] = beta[o] - (float)mean * sc;
}

// ---------------- kernel 7: normalize + leaky relu + max over k -> out[b][o][n] --------
__global__ void k_out(float* __restrict__ out) {
    int b = blockIdx.y;
    int n0 = blockIdx.x * 32;
    int tid = threadIdx.x;
    int o = tid & 63, nq = tid >> 6;
    __shared__ float sm[64 * 33];
    float sc = g_scale[o], sh = g_shift[o];
    for (int j = 0; j < 8; j++) {
        int nl = nq * 8 + j;
        int n = n0 + nl;
        float bse = g_Bse[((size_t)b * Nn + n) * On + o];
        const int* ip = g_idx + (b * Nn + n) * Kn;
        float mx = -FLT_MAX;
#pragma unroll
        for (int k = 0; k < Kn; k++) {
            int m = ip[k];
            float y  = g_U[((size_t)b * Nn + m) * On + o] + bse;
            float yn = fmaf(y, sc, sh);
            float a  = (yn >= 0.f) ? yn : 0.2f * yn;
            mx = fmaxf(mx, a);
        }
        sm[o * 33 + nl] = mx;
    }
    __syncthreads();
    int nl2 = tid & 31, og = tid >> 5;
#pragma unroll
    for (int j = 0; j < 8; j++) {
        int o2 = og * 8 + j;
        out[((size_t)b * On + o2) * Nn + n0 + nl2] = sm[o2 * 33 + nl2];
    }
}

// ---------------- launch ----------------
extern "C" void kernel_launch(void* const* d_in, const int* in_sizes, int n_in,
                              void* d_out, int out_size) {
    const float* x     = (const float*)d_in[0];
    const float* W     = (const float*)d_in[1];
    const float* gamma = (const float*)d_in[2];
    const float* beta  = (const float*)d_in[3];
    float* out = (float*)d_out;

    k_zero<<<1, 64>>>();
    k_xx<<<(Bn * Nn) / 256, 256>>>(x);

    dim3 gg(136, 16);                 // triangular tile set, 128x128 tiles
    k_gram<<<gg, 256>>>(x);

    k_topk<<<Bn * Nn, 256>>>();

    dim3 guv(Nn / 64, Bn);
    k_uv<<<guv, 256>>>(x, W);

    dim3 gst(16, Bn);
    k_stats<<<gst, 256>>>();

    k_fin<<<1, 64>>>(gamma, beta);

    dim3 go(Nn / 32, Bn);
    k_out<<<go, 256>>>(out);
}